// round 5
// baseline (speedup 1.0000x reference)
#include <cuda_runtime.h>
#include <stdint.h>

#define D 128
#define K 16
#define TPB 128
#define WARPS 4
#define WROWS 128               // rows per warp work-unit (R=4 per thread)
#define CH 8                    // columns per chunk
#define NCH 16                  // chunks per unit (D/CH)
#define ROWSTRIDE 48            // 32B data + 16B pad: conflict-free LDS.128, 16B-aligned
#define STAGE_BYTES (WROWS * ROWSTRIDE)      // 6144
#define NSTAGE 3
#define WARP_STAGING (NSTAGE * STAGE_BYTES)  // 18432
#define SMEM_HDR 8448           // A (8192) + c/U + pad
#define SMEM_TOTAL (SMEM_HDR + WARPS * WARP_STAGING)  // 82176 -> 2 CTAs/SM
#define NBLK 296                // persistent: 148 SMs x 2 CTAs

// Precomputed A in (cp, k) pair-major: gAp[cp*K + k] is float2 = (A[k][2cp], A[k][2cp+1])
__device__ __align__(16) float gAp[(D / 2) * K * 2];
__device__ float gC[K];

// ---------------- helpers ----------------
__device__ __forceinline__ void ffma2(unsigned long long& c, unsigned long long a, unsigned long long b) {
    asm("fma.rn.f32x2 %0, %1, %2, %0;" : "+l"(c) : "l"(a), "l"(b));
}
__device__ __forceinline__ void unpack2(float& lo, float& hi, unsigned long long v) {
    asm("mov.b64 {%0, %1}, %2;" : "=f"(lo), "=f"(hi) : "l"(v));
}
__device__ __forceinline__ void cp_async16(uint32_t dst, const void* src, int src_bytes) {
    asm volatile("cp.async.cg.shared.global [%0], [%1], 16, %2;\n"
                 :: "r"(dst), "l"(src), "r"(src_bytes));
}
__device__ __forceinline__ void cp_commit() {
    asm volatile("cp.async.commit_group;\n" ::: "memory");
}
__device__ __forceinline__ void cp_wait2() {
    asm volatile("cp.async.wait_group 2;\n" ::: "memory");
}

// ---------------- merged prep ----------------
// blocks 0..127: A rows (warp computes 4 rows, MLP=4); block 128: c[k]
__global__ void ntn_prep(const float* __restrict__ x2,
                         const float* __restrict__ V,
                         const float* __restrict__ W,
                         const float* __restrict__ b) {
    const int lane = threadIdx.x & 31;
    const int wid = threadIdx.x >> 5;
    const float4 x4 = ((const float4*)x2)[lane];

    if (blockIdx.x < 128) {
        const int gw = blockIdx.x * 4 + wid;        // 0..511, rows 4gw..4gw+3
        float4 w4[4];
#pragma unroll
        for (int rr = 0; rr < 4; rr++)
            w4[rr] = ((const float4*)(W + (size_t)(gw * 4 + rr) * D))[lane];
        float dots[4];
#pragma unroll
        for (int rr = 0; rr < 4; rr++)
            dots[rr] = w4[rr].x * x4.x + w4[rr].y * x4.y + w4[rr].z * x4.z + w4[rr].w * x4.w;
#pragma unroll
        for (int s = 16; s > 0; s >>= 1) {
#pragma unroll
            for (int rr = 0; rr < 4; rr++)
                dots[rr] += __shfl_xor_sync(0xffffffffu, dots[rr], s);
        }
        if (lane == 0) {
#pragma unroll
            for (int rr = 0; rr < 4; rr++) {
                const int row = gw * 4 + rr;        // = k*128 + d
                const int k = row >> 7, d = row & (D - 1);
                gAp[((d >> 1) * K + k) * 2 + (d & 1)] = V[(size_t)k * 2 * D + d] + dots[rr];
            }
        }
    } else {
#pragma unroll
        for (int kk = 0; kk < 4; kk++) {
            const int k = wid * 4 + kk;
            const float4 v4 = ((const float4*)(V + (size_t)k * 2 * D + D))[lane];
            float dot = v4.x * x4.x + v4.y * x4.y + v4.z * x4.z + v4.w * x4.w;
#pragma unroll
            for (int s = 16; s > 0; s >>= 1)
                dot += __shfl_xor_sync(0xffffffffu, dot, s);
            if (lane == 0) gC[k] = dot + b[k];
        }
    }
}

// ---------------- main: persistent, per-warp units, 3-stage per-warp cp.async pipeline ----------------
__global__ __launch_bounds__(TPB)
void ntn_main(const float* __restrict__ x1,
              const float* __restrict__ U,
              float* __restrict__ out, int n, int nunits, int nw) {
    extern __shared__ __align__(16) char smem_raw[];
    unsigned long long* sA = (unsigned long long*)smem_raw;   // 1024 ull, cp-major
    float* sC = (float*)(smem_raw + 8192);
    float* sU = sC + K;
    char* staging = smem_raw + SMEM_HDR;

    const int tid = threadIdx.x;
    const int wid = tid >> 5;
    const int lane = tid & 31;

    char* wstage = staging + (size_t)wid * WARP_STAGING;
    const uint32_t wstage_u32 = (uint32_t)__cvta_generic_to_shared(wstage);

    // per-warp chunk issue: 128 rows x 8 cols (32B/row) -> 8 cp.async16 per lane
    auto issue = [&](int unit, int ch, int buf) {
        const uint32_t base = wstage_u32 + (uint32_t)buf * STAGE_BYTES;
        const int rowbase = unit * WROWS;
#pragma unroll
        for (int i = 0; i < 8; i++) {
            const int idx = i * 32 + lane;
            const int r = idx >> 1;         // 0..127
            const int c = idx & 1;          // float4 within 32B row-chunk
            const int grow = rowbase + r;
            const int ok = (grow < n);
            const float* src = x1 + (size_t)(ok ? grow : 0) * D + ch * CH + c * 4;
            cp_async16(base + (uint32_t)(r * ROWSTRIDE + c * 16), src, ok ? 16 : 0);
        }
    };

    const int gw0 = blockIdx.x * WARPS + wid;

    // prologue: 2 chunks in flight
    if (gw0 < nunits) { issue(gw0, 0, 0); cp_commit(); issue(gw0, 1, 1); cp_commit(); }
    else { cp_commit(); cp_commit(); }

    // header: A, c, U (single block barrier in whole kernel)
    {
        const unsigned long long* gAu = (const unsigned long long*)gAp;
#pragma unroll
        for (int i = 0; i < 8; i++) sA[tid + i * TPB] = gAu[tid + i * TPB];
        if (tid < K) { sC[tid] = gC[tid]; sU[tid] = U[tid]; }
    }
    __syncthreads();

    int buf = 0;
    for (int u = gw0; u < nunits; u += nw) {
        unsigned long long acc[4][K];
#pragma unroll
        for (int rr = 0; rr < 4; rr++)
#pragma unroll
            for (int k = 0; k < K; k++) acc[rr][k] = 0ull;

        for (int ch = 0; ch < NCH; ch++) {
            // issue 2 chunks ahead in the stream
            int ch2 = ch + 2, u2 = u;
            if (ch2 >= NCH) { ch2 -= NCH; u2 += nw; }
            int ib = buf + 2; if (ib >= NSTAGE) ib -= NSTAGE;
            if (u2 < nunits) issue(u2, ch2, ib);
            cp_commit();                 // commit every iter (empty ok) -> uniform counting
            cp_wait2();                  // <=2 pending => current chunk landed
            __syncwarp();

            const char* wb = wstage + (size_t)buf * STAGE_BYTES;
            unsigned long long xv[4][4];
#pragma unroll
            for (int rr = 0; rr < 4; rr++) {
                const char* rp = wb + (size_t)(rr * 32 + lane) * ROWSTRIDE;
                const ulonglong2 q0 = *(const ulonglong2*)(rp);
                const ulonglong2 q1 = *(const ulonglong2*)(rp + 16);
                xv[rr][0] = q0.x; xv[rr][1] = q0.y; xv[rr][2] = q1.x; xv[rr][3] = q1.y;
            }
#pragma unroll
            for (int cpl = 0; cpl < 4; cpl++) {
                const ulonglong2* Ab = (const ulonglong2*)(sA + (ch * 4 + cpl) * K);
#pragma unroll
                for (int k2 = 0; k2 < 8; k2++) {
                    const ulonglong2 a2 = Ab[k2];       // broadcast LDS.128, feeds 8 FFMA2
#pragma unroll
                    for (int rr = 0; rr < 4; rr++) {
                        ffma2(acc[rr][2 * k2],     xv[rr][cpl], a2.x);
                        ffma2(acc[rr][2 * k2 + 1], xv[rr][cpl], a2.y);
                    }
                }
            }
            __syncwarp();               // all lanes done with buf before re-issue
            if (++buf == NSTAGE) buf = 0;
        }

        // epilogue (overlaps next unit's first 2 chunks already in flight)
#pragma unroll
        for (int rr = 0; rr < 4; rr++) {
            float res = 0.f;
#pragma unroll
            for (int k = 0; k < K; k++) {
                float lo, hi;
                unpack2(lo, hi, acc[rr][k]);
                const float s = lo + hi + sC[k];
                res = fmaf(fmaxf(s, 0.f), sU[k], res);
            }
            const int row = u * WROWS + rr * 32 + lane;
            if (row < n) out[row] = res;
        }
    }
    asm volatile("cp.async.wait_all;\n" ::: "memory");
}

// ---------------- launch ----------------
extern "C" void kernel_launch(void* const* d_in, const int* in_sizes, int n_in,
                              void* d_out, int out_size) {
    const float* x1 = nullptr; const float* x2 = nullptr; const float* V = nullptr;
    const float* W = nullptr;  const float* b = nullptr;  const float* U = nullptr;
    int n16 = 0;
    for (int i = 0; i < n_in; i++) {
        const int s = in_sizes[i];
        const float* p = (const float*)d_in[i];
        if (s == 128) x2 = p;
        else if (s == 4096) V = p;
        else if (s == 262144) W = p;
        else if (s == 16) { if (n16++ == 0) b = p; else U = p; }
        else x1 = p;
    }
    int n = 0;
    for (int i = 0; i < n_in; i++) if ((const float*)d_in[i] == x1) n = in_sizes[i] / D;

    float* out = (float*)d_out;

    ntn_prep<<<129, TPB>>>(x2, V, W, b);

    const int nunits = (n + WROWS - 1) / WROWS;
    int blocks = (nunits + WARPS - 1) / WARPS;
    if (blocks > NBLK) blocks = NBLK;
    const int nw = blocks * WARPS;
    cudaFuncSetAttribute(ntn_main, cudaFuncAttributeMaxDynamicSharedMemorySize, SMEM_TOTAL);
    ntn_main<<<blocks, TPB, SMEM_TOTAL>>>(x1, U, out, n, nunits, nw);
}

// round 6
// speedup vs baseline: 1.0316x; 1.0316x over previous
#include <cuda_runtime.h>
#include <stdint.h>

#define D 128
#define K 16
#define TPB 128
#define WARPS 4
#define WROWS 64                // rows per warp work-unit (R=2 per thread)
#define CH 8                    // columns per chunk
#define NCH 16                  // chunks per unit (D/CH)
#define ROWSTRIDE 48            // 32B data + 16B pad: conflict-free LDS.128, 16B aligned
#define STAGE_BYTES (WROWS * ROWSTRIDE)      // 3072
#define NSTAGE 3
#define WARP_STAGING (NSTAGE * STAGE_BYTES)  // 9216
#define SMEM_HDR 8448           // A (8192) + c/U + pad
#define SMEM_TOTAL (SMEM_HDR + WARPS * WARP_STAGING)  // 45312 -> 4 CTAs/SM at 128 regs
#define NBLK 592                // persistent: 148 SMs x 4 CTAs

// Precomputed A in (cp, k) pair-major: gAp[cp*K + k] is float2 = (A[k][2cp], A[k][2cp+1])
__device__ __align__(16) float gAp[(D / 2) * K * 2];
__device__ float gC[K];

// ---------------- helpers ----------------
__device__ __forceinline__ void ffma2(unsigned long long& c, unsigned long long a, unsigned long long b) {
    asm("fma.rn.f32x2 %0, %1, %2, %0;" : "+l"(c) : "l"(a), "l"(b));
}
__device__ __forceinline__ void unpack2(float& lo, float& hi, unsigned long long v) {
    asm("mov.b64 {%0, %1}, %2;" : "=f"(lo), "=f"(hi) : "l"(v));
}
__device__ __forceinline__ void cp_async16(uint32_t dst, const void* src, int src_bytes) {
    asm volatile("cp.async.cg.shared.global [%0], [%1], 16, %2;\n"
                 :: "r"(dst), "l"(src), "r"(src_bytes));
}
__device__ __forceinline__ void cp_commit() {
    asm volatile("cp.async.commit_group;\n" ::: "memory");
}
__device__ __forceinline__ void cp_wait2() {
    asm volatile("cp.async.wait_group 2;\n" ::: "memory");
}

// ---------------- merged prep (single launch, ~2us) ----------------
// blocks 0..127: A rows (warp computes 4 rows, MLP=4); block 128: c[k]
__global__ void ntn_prep(const float* __restrict__ x2,
                         const float* __restrict__ V,
                         const float* __restrict__ W,
                         const float* __restrict__ b) {
    const int lane = threadIdx.x & 31;
    const int wid = threadIdx.x >> 5;
    const float4 x4 = ((const float4*)x2)[lane];

    if (blockIdx.x < 128) {
        const int gw = blockIdx.x * 4 + wid;        // 0..511, rows 4gw..4gw+3
        float4 w4[4];
#pragma unroll
        for (int rr = 0; rr < 4; rr++)
            w4[rr] = ((const float4*)(W + (size_t)(gw * 4 + rr) * D))[lane];
        float dots[4];
#pragma unroll
        for (int rr = 0; rr < 4; rr++)
            dots[rr] = w4[rr].x * x4.x + w4[rr].y * x4.y + w4[rr].z * x4.z + w4[rr].w * x4.w;
#pragma unroll
        for (int s = 16; s > 0; s >>= 1) {
#pragma unroll
            for (int rr = 0; rr < 4; rr++)
                dots[rr] += __shfl_xor_sync(0xffffffffu, dots[rr], s);
        }
        if (lane == 0) {
#pragma unroll
            for (int rr = 0; rr < 4; rr++) {
                const int row = gw * 4 + rr;        // = k*128 + d
                const int k = row >> 7, d = row & (D - 1);
                gAp[((d >> 1) * K + k) * 2 + (d & 1)] = V[(size_t)k * 2 * D + d] + dots[rr];
            }
        }
    } else {
#pragma unroll
        for (int kk = 0; kk < 4; kk++) {
            const int k = wid * 4 + kk;
            const float4 v4 = ((const float4*)(V + (size_t)k * 2 * D + D))[lane];
            float dot = v4.x * x4.x + v4.y * x4.y + v4.z * x4.z + v4.w * x4.w;
#pragma unroll
            for (int s = 16; s > 0; s >>= 1)
                dot += __shfl_xor_sync(0xffffffffu, dot, s);
            if (lane == 0) gC[k] = dot + b[k];
        }
    }
}

// ---------------- main: persistent per-warp units, 3-stage per-warp cp.async pipeline ----------------
__global__ __launch_bounds__(TPB, 4)
void ntn_main(const float* __restrict__ x1,
              const float* __restrict__ U,
              float* __restrict__ out, int n, int nunits, int nw) {
    extern __shared__ __align__(16) char smem_raw[];
    unsigned long long* sA = (unsigned long long*)smem_raw;   // 1024 ull, cp-major
    float* sC = (float*)(smem_raw + 8192);
    float* sU = sC + K;

    const int tid = threadIdx.x;
    const int wid = tid >> 5;
    const int lane = tid & 31;

    const uint32_t smem_u32 = (uint32_t)__cvta_generic_to_shared(smem_raw);
    const uint32_t wstage_u32 = smem_u32 + SMEM_HDR + (uint32_t)wid * WARP_STAGING;

    // per-warp chunk issue: 64 rows x 8 cols (32B/row) -> 4 cp.async16 per lane
    // contiguous mapping: lanes 2l,2l+1 cover row l's 32B -> 16 lines per instr
    auto issue = [&](int unit, int ch, int buf) {
        const uint32_t base = wstage_u32 + (uint32_t)buf * STAGE_BYTES;
        const int rowbase = unit * WROWS;
#pragma unroll
        for (int i = 0; i < 4; i++) {
            const int idx = i * 32 + lane;
            const int r = idx >> 1;         // 0..63
            const int c = idx & 1;          // float4 within 32B row-chunk
            const int grow = rowbase + r;
            const int ok = (grow < n);
            const float* src = x1 + (size_t)(ok ? grow : 0) * D + ch * CH + c * 4;
            cp_async16(base + (uint32_t)(r * ROWSTRIDE + c * 16), src, ok ? 16 : 0);
        }
    };

    const int gw0 = blockIdx.x * WARPS + wid;

    // prologue: 2 chunks in flight before header load
    if (gw0 < nunits) { issue(gw0, 0, 0); cp_commit(); issue(gw0, 1, 1); cp_commit(); }
    else { cp_commit(); cp_commit(); }

    // header: A, c, U (single block barrier in whole kernel)
    {
        const unsigned long long* gAu = (const unsigned long long*)gAp;
#pragma unroll
        for (int i = 0; i < 8; i++) sA[tid + i * TPB] = gAu[tid + i * TPB];
        if (tid < K) { sC[tid] = gC[tid]; sU[tid] = U[tid]; }
    }
    __syncthreads();

    int buf = 0;
    for (int u = gw0; u < nunits; u += nw) {
        unsigned long long acc0[K], acc1[K];
#pragma unroll
        for (int k = 0; k < K; k++) { acc0[k] = 0ull; acc1[k] = 0ull; }

        for (int ch = 0; ch < NCH; ch++) {
            // issue 2 chunks ahead in the stream (wraps into next unit)
            int ch2 = ch + 2, u2 = u;
            if (ch2 >= NCH) { ch2 -= NCH; u2 += nw; }
            int ib = buf + 2; if (ib >= NSTAGE) ib -= NSTAGE;
            if (u2 < nunits) issue(u2, ch2, ib);
            cp_commit();                 // commit every iter (empty ok) -> uniform counting
            cp_wait2();                  // <=2 pending => current chunk landed (warp-scope scoreboard)

            const uint32_t wb = wstage_u32 + (uint32_t)buf * STAGE_BYTES;
            // 2 rows per thread: rows lane, lane+32 ; 2 x LDS.128 each (32B)
            ulonglong2 qa0, qa1, qb0, qb1;
            {
                const uint32_t rp0 = wb + (uint32_t)lane * ROWSTRIDE;
                const uint32_t rp1 = wb + (uint32_t)(lane + 32) * ROWSTRIDE;
                asm volatile("ld.shared.v2.u64 {%0,%1}, [%2];" : "=l"(qa0.x), "=l"(qa0.y) : "r"(rp0));
                asm volatile("ld.shared.v2.u64 {%0,%1}, [%2];" : "=l"(qa1.x), "=l"(qa1.y) : "r"(rp0 + 16));
                asm volatile("ld.shared.v2.u64 {%0,%1}, [%2];" : "=l"(qb0.x), "=l"(qb0.y) : "r"(rp1));
                asm volatile("ld.shared.v2.u64 {%0,%1}, [%2];" : "=l"(qb1.x), "=l"(qb1.y) : "r"(rp1 + 16));
            }
            const unsigned long long xa[4] = { qa0.x, qa0.y, qa1.x, qa1.y };
            const unsigned long long xb[4] = { qb0.x, qb0.y, qb1.x, qb1.y };

#pragma unroll
            for (int cpl = 0; cpl < 4; cpl++) {
                const ulonglong2* Ab = (const ulonglong2*)(sA + (ch * 4 + cpl) * K);
#pragma unroll
                for (int k2 = 0; k2 < 8; k2++) {
                    const ulonglong2 a2 = Ab[k2];       // broadcast LDS.128 -> 4 FFMA2
                    ffma2(acc0[2 * k2],     xa[cpl], a2.x);
                    ffma2(acc0[2 * k2 + 1], xa[cpl], a2.y);
                    ffma2(acc1[2 * k2],     xb[cpl], a2.x);
                    ffma2(acc1[2 * k2 + 1], xb[cpl], a2.y);
                }
            }
            __syncwarp();               // WAR: all lanes done with buf before it is re-issued
            if (++buf == NSTAGE) buf = 0;
        }

        // epilogue (next unit's first 2 chunks already in flight)
        float res0 = 0.f, res1 = 0.f;
#pragma unroll
        for (int k = 0; k < K; k++) {
            float lo, hi;
            unpack2(lo, hi, acc0[k]);
            const float s0 = lo + hi + sC[k];
            res0 = fmaf(fmaxf(s0, 0.f), sU[k], res0);
            unpack2(lo, hi, acc1[k]);
            const float s1 = lo + hi + sC[k];
            res1 = fmaf(fmaxf(s1, 0.f), sU[k], res1);
        }
        const int ra = u * WROWS + lane;
        const int rb = ra + 32;
        if (ra < n) out[ra] = res0;
        if (rb < n) out[rb] = res1;
    }
    asm volatile("cp.async.wait_all;\n" ::: "memory");
}

// ---------------- launch ----------------
extern "C" void kernel_launch(void* const* d_in, const int* in_sizes, int n_in,
                              void* d_out, int out_size) {
    const float* x1 = nullptr; const float* x2 = nullptr; const float* V = nullptr;
    const float* W = nullptr;  const float* b = nullptr;  const float* U = nullptr;
    int n16 = 0;
    for (int i = 0; i < n_in; i++) {
        const int s = in_sizes[i];
        const float* p = (const float*)d_in[i];
        if (s == 128) x2 = p;
        else if (s == 4096) V = p;
        else if (s == 262144) W = p;
        else if (s == 16) { if (n16++ == 0) b = p; else U = p; }
        else x1 = p;
    }
    int n = 0;
    for (int i = 0; i < n_in; i++) if ((const float*)d_in[i] == x1) n = in_sizes[i] / D;

    float* out = (float*)d_out;

    ntn_prep<<<129, TPB>>>(x2, V, W, b);

    const int nunits = (n + WROWS - 1) / WROWS;
    int blocks = (nunits + WARPS - 1) / WARPS;
    if (blocks > NBLK) blocks = NBLK;
    const int nw = blocks * WARPS;
    cudaFuncSetAttribute(ntn_main, cudaFuncAttributeMaxDynamicSharedMemorySize, SMEM_TOTAL);
    ntn_main<<<blocks, TPB, SMEM_TOTAL>>>(x1, U, out, n, nunits, nw);
}